// round 14
// baseline (speedup 1.0000x reference)
#include <cuda_runtime.h>
#include <cuda_fp16.h>
#include <cuda_bf16.h>

#define NN 100000
#define EE 3200000
#define GG 512
#define NBLK 391   // (NN+255)/256

// ---------------- scratch (device globals; no allocations) ----------------
__device__ float4 g_bufA4[NN * 16];   // layer-4 MLP output (for pooling), fp32
__device__ uint2  g_bufH0[NN * 16];   // fp16 feature table, buffer 0 (128B rows)
__device__ uint2  g_bufH1[NN * 16];   // fp16 feature table, buffer 1
__device__ int    g_deg[NN];
__device__ int    g_rowptr[NN + 1];
__device__ int    g_cursor[NN];
__device__ int    g_col[EE];
__device__ int    g_gs[GG];
__device__ int    g_ge[GG];
__device__ float  g_bn[128];          // [0:64) sum, [64:128) sumsq
__device__ float  g_sc[64];           // BN folded scale
__device__ float  g_sh[64];           // BN folded shift
__device__ int    g_bsum[512];
__device__ int    g_boff[512];

// ---------------- f32x2 helpers ----------------
__device__ __forceinline__ unsigned long long pk2(float lo, float hi) {
    unsigned long long r;
    asm("mov.b64 %0,{%1,%2};" : "=l"(r) : "f"(lo), "f"(hi));
    return r;
}
__device__ __forceinline__ unsigned long long ffma2(unsigned long long a,
                                                    unsigned long long b,
                                                    unsigned long long c) {
    unsigned long long d;
    asm("fma.rn.f32x2 %0,%1,%2,%3;" : "=l"(d) : "l"(a), "l"(b), "l"(c));
    return d;
}
__device__ __forceinline__ void upk2(unsigned long long v, float& lo, float& hi) {
    asm("mov.b64 {%0,%1},%2;" : "=f"(lo), "=f"(hi) : "l"(v));
}

// ---------------- init ----------------
__global__ void k_init() {
    int i = blockIdx.x * blockDim.x + threadIdx.x;
    if (i < NN) g_deg[i] = 0;
    if (i < GG) { g_gs[i] = -1; g_ge[i] = -1; }
    if (i < 128) g_bn[i] = 0.f;
}

// ---------------- x -> fp16 table (buffer 0) AND edge histogram (EE == NN*32) --
__global__ void k_toh_hist(const float2* __restrict__ x2, const int* __restrict__ ei) {
    int i = blockIdx.x * blockDim.x + threadIdx.x;
    if (i < NN * 32) {
        float2 v = x2[i];
        ((__half2*)g_bufH0)[i] = __floats2half2_rn(v.x, v.y);
    }
    if (i < EE) atomicAdd(&g_deg[ei[EE + i]], 1);
}

// ---------------- graph bounds + per-block degree sums (both grid NBLK) -------
__global__ void k_bounds_bsum(const int* __restrict__ batch) {
    __shared__ int s[256];
    int t = threadIdx.x;
    int i = blockIdx.x * 256 + t;
    if (i < NN) {
        int b = batch[i];
        if (i == 0 || batch[i - 1] != b) g_gs[b] = i;
        if (i == NN - 1 || batch[i + 1] != b) g_ge[b] = i;
    }
    s[t] = (i < NN) ? g_deg[i] : 0;
    __syncthreads();
#pragma unroll
    for (int off = 128; off > 0; off >>= 1) {
        if (t < off) s[t] += s[t + off];
        __syncthreads();
    }
    if (t == 0) g_bsum[blockIdx.x] = s[0];
}

__global__ void k_scanb() {
    __shared__ int s[512];
    int t = threadIdx.x;
    int v = (t < NBLK) ? g_bsum[t] : 0;
    s[t] = v;
    __syncthreads();
    for (int off = 1; off < 512; off <<= 1) {
        int u = (t >= off) ? s[t - off] : 0;
        __syncthreads();
        s[t] += u;
        __syncthreads();
    }
    if (t < NBLK) g_boff[t] = s[t] - v;  // exclusive
}

__global__ void k_scan2() {
    __shared__ int s[256];
    int t = threadIdx.x;
    int i = blockIdx.x * 256 + t;
    int v = (i < NN) ? g_deg[i] : 0;
    s[t] = v;
    __syncthreads();
    for (int off = 1; off < 256; off <<= 1) {
        int u = (t >= off) ? s[t - off] : 0;
        __syncthreads();
        s[t] += u;
        __syncthreads();
    }
    int base = g_boff[blockIdx.x];
    int ex = base + s[t] - v;
    if (i < NN) { g_rowptr[i] = ex; g_cursor[i] = ex; }
    if (i == NN - 1) g_rowptr[NN] = base + s[t];
}

__global__ void k_scatter(const int* __restrict__ ei) {
    int e = blockIdx.x * blockDim.x + threadIdx.x;
    if (e >= EE) return;
    int s = ei[e];
    int d = ei[EE + e];
    int p = atomicAdd(&g_cursor[d], 1);
    g_col[p] = s;
}

// ---------------- BN stats -> folded affine, re-zero accumulators ----------------
__global__ void k_bnstats(const float* __restrict__ gam, const float* __restrict__ bet) {
    int c = threadIdx.x;  // 64 threads
    float inv = 1.0f / (float)NN;
    float mu = g_bn[c] * inv;
    float var = g_bn[64 + c] * inv - mu * mu;
    float s = gam[c] * rsqrtf(var + 1e-5f);
    g_sc[c] = s;
    g_sh[c] = bet[c] - mu * s;
    g_bn[c] = 0.f;
    g_bn[64 + c] = 0.f;
}

// ================= FUSED: gather(agg, BN-fold) + MLP + BN partial sums =========
// 64-node tile per block, 256 threads. Double-buffered fp16 table (Hr -> Hw).
// Gather: half-warp per node (4 nodes serial per half-warp), 4-edge windows with
// SOFTWARE-PIPELINED column indices (next window's cols load under current rows).
__global__ __launch_bounds__(256) void k_fused(const float* __restrict__ wa,
                                               const float* __restrict__ ba,
                                               const float* __restrict__ wb,
                                               const float* __restrict__ bb,
                                               const float* __restrict__ epsp,
                                               const uint2* __restrict__ Hr,
                                               uint2* __restrict__ Hw,
                                               int fold, int wfp32) {
    __shared__ float sT[64][68];     // transposed tile sT[k][node]
    __shared__ float sW[64 * 64];    // weights; later reused as BN-reduce buffer
    __shared__ float sB[64];

    float* __restrict__ out = (float*)g_bufA4;

    int tid = threadIdx.x;
    int n0 = blockIdx.x * 64;
    float e1 = 1.0f + *epsp;

    // issue wa/ba loads first so they land under gather latency
    for (int idx = tid; idx < 4096; idx += 256) sW[idx] = wa[idx];
    if (tid < 64) sB[tid] = ba[tid];

    // ---- phase 0: gather + fold (pipelined col indices, 4 rows in flight) ----
    {
        int hw = tid >> 4;       // half-warp id 0..15
        int li = tid & 15;       // lane within half-warp: 4 channels
        float4 fsc, fsh;
        if (fold) {
            fsc = *(const float4*)&g_sc[li * 4];
            fsh = *(const float4*)&g_sh[li * 4];
        }
#pragma unroll
        for (int rr = 0; rr < 4; rr++) {
            int r = hw + rr * 16;
            int node = n0 + r;
            float4 a0 = make_float4(0.f, 0.f, 0.f, 0.f);
            if (node < NN) {
                uint2 sv = Hr[node * 16 + li];
                float2 s0 = __half22float2(*(const __half2*)&sv.x);
                float2 s1 = __half22float2(*(const __half2*)&sv.y);
                a0 = make_float4(e1 * s0.x, e1 * s0.y, e1 * s1.x, e1 * s1.y);
                float4 a1 = make_float4(0.f, 0.f, 0.f, 0.f);
                float4 a2 = make_float4(0.f, 0.f, 0.f, 0.f);
                float4 a3 = make_float4(0.f, 0.f, 0.f, 0.f);
                int s = g_rowptr[node], e = g_rowptr[node + 1];
                int j = s;
                int c0, c1, c2, c3;
                if (j + 3 < e) {
                    c0 = __ldg(&g_col[j]);
                    c1 = __ldg(&g_col[j + 1]);
                    c2 = __ldg(&g_col[j + 2]);
                    c3 = __ldg(&g_col[j + 3]);
                }
                while (j + 3 < e) {
                    int m0 = c0, m1 = c1, m2 = c2, m3 = c3;
                    int jn = j + 4;
                    if (jn + 3 < e) {  // prefetch next window's indices
                        c0 = __ldg(&g_col[jn]);
                        c1 = __ldg(&g_col[jn + 1]);
                        c2 = __ldg(&g_col[jn + 2]);
                        c3 = __ldg(&g_col[jn + 3]);
                    }
                    uint2 v0 = Hr[m0 * 16 + li];
                    uint2 v1 = Hr[m1 * 16 + li];
                    uint2 v2 = Hr[m2 * 16 + li];
                    uint2 v3 = Hr[m3 * 16 + li];
                    float2 p0 = __half22float2(*(const __half2*)&v0.x);
                    float2 p1 = __half22float2(*(const __half2*)&v0.y);
                    a0.x += p0.x; a0.y += p0.y; a0.z += p1.x; a0.w += p1.y;
                    float2 q0 = __half22float2(*(const __half2*)&v1.x);
                    float2 q1 = __half22float2(*(const __half2*)&v1.y);
                    a1.x += q0.x; a1.y += q0.y; a1.z += q1.x; a1.w += q1.y;
                    float2 u0 = __half22float2(*(const __half2*)&v2.x);
                    float2 u1 = __half22float2(*(const __half2*)&v2.y);
                    a2.x += u0.x; a2.y += u0.y; a2.z += u1.x; a2.w += u1.y;
                    float2 w0 = __half22float2(*(const __half2*)&v3.x);
                    float2 w1 = __half22float2(*(const __half2*)&v3.y);
                    a3.x += w0.x; a3.y += w0.y; a3.z += w1.x; a3.w += w1.y;
                    j = jn;
                }
                for (; j < e; j++) {
                    int m0 = __ldg(&g_col[j]);
                    uint2 v0 = Hr[m0 * 16 + li];
                    float2 p0 = __half22float2(*(const __half2*)&v0.x);
                    float2 p1 = __half22float2(*(const __half2*)&v0.y);
                    a0.x += p0.x; a0.y += p0.y; a0.z += p1.x; a0.w += p1.y;
                }
                a0.x += a1.x + a2.x + a3.x;
                a0.y += a1.y + a2.y + a3.y;
                a0.z += a1.z + a2.z + a3.z;
                a0.w += a1.w + a2.w + a3.w;
                if (fold) {
                    float coef = e1 + (float)(e - s);
                    a0.x = fmaf(a0.x, fsc.x, coef * fsh.x);
                    a0.y = fmaf(a0.y, fsc.y, coef * fsh.y);
                    a0.z = fmaf(a0.z, fsc.z, coef * fsh.z);
                    a0.w = fmaf(a0.w, fsc.w, coef * fsh.w);
                }
            }
            sT[4 * li + 0][r] = a0.x;
            sT[4 * li + 1][r] = a0.y;
            sT[4 * li + 2][r] = a0.z;
            sT[4 * li + 3][r] = a0.w;
        }
    }
    __syncthreads();

    int tx = tid & 15;   // channel quad
    int ty = tid >> 4;   // node quad

    unsigned long long accP[4][2];
#pragma unroll
    for (int i = 0; i < 4; i++) { accP[i][0] = 0ULL; accP[i][1] = 0ULL; }

#pragma unroll 16
    for (int k = 0; k < 64; k++) {
        float4 a = *(const float4*)&sT[k][ty * 4];
        ulonglong2 b2 = *(const ulonglong2*)(sW + k * 64 + tx * 4);
        float av[4] = {a.x, a.y, a.z, a.w};
#pragma unroll
        for (int i = 0; i < 4; i++) {
            unsigned long long aa = pk2(av[i], av[i]);
            accP[i][0] = ffma2(aa, b2.x, accP[i][0]);
            accP[i][1] = ffma2(aa, b2.y, accP[i][1]);
        }
    }
    __syncthreads();  // all reads of sT/sW done

    // mid = relu(acc + ba), stored transposed back into sT
    {
        float m[4][4];
#pragma unroll
        for (int i = 0; i < 4; i++) {
            upk2(accP[i][0], m[i][0], m[i][1]);
            upk2(accP[i][1], m[i][2], m[i][3]);
        }
#pragma unroll
        for (int j = 0; j < 4; j++) {
            float bias = sB[4 * tx + j];
            float4 w;
            w.x = fmaxf(m[0][j] + bias, 0.f);
            w.y = fmaxf(m[1][j] + bias, 0.f);
            w.z = fmaxf(m[2][j] + bias, 0.f);
            w.w = fmaxf(m[3][j] + bias, 0.f);
            *(float4*)&sT[4 * tx + j][4 * ty] = w;
        }
    }
    for (int idx = tid; idx < 4096; idx += 256) sW[idx] = wb[idx];
    if (tid < 64) sB[tid] = bb[tid];
    __syncthreads();

#pragma unroll
    for (int i = 0; i < 4; i++) { accP[i][0] = 0ULL; accP[i][1] = 0ULL; }

#pragma unroll 16
    for (int k = 0; k < 64; k++) {
        float4 a = *(const float4*)&sT[k][ty * 4];
        ulonglong2 b2 = *(const ulonglong2*)(sW + k * 64 + tx * 4);
        float av[4] = {a.x, a.y, a.z, a.w};
#pragma unroll
        for (int i = 0; i < 4; i++) {
            unsigned long long aa = pk2(av[i], av[i]);
            accP[i][0] = ffma2(aa, b2.x, accP[i][0]);
            accP[i][1] = ffma2(aa, b2.y, accP[i][1]);
        }
    }
    __syncthreads();  // sW reads done -> safe to reuse as sRed

    float (*sRed)[128] = (float (*)[128])sW;  // alias

    // out = relu(acc2 + bb): fp16 table write + optional fp32 write + BN partials
    float m2[4][4];
#pragma unroll
    for (int i = 0; i < 4; i++) {
        upk2(accP[i][0], m2[i][0], m2[i][1]);
        upk2(accP[i][1], m2[i][2], m2[i][3]);
    }
    float psum[4] = {0.f, 0.f, 0.f, 0.f};
    float psq[4] = {0.f, 0.f, 0.f, 0.f};
#pragma unroll
    for (int i = 0; i < 4; i++) {
        int node = n0 + 4 * ty + i;
        float o[4];
#pragma unroll
        for (int j = 0; j < 4; j++) o[j] = fmaxf(m2[i][j] + sB[4 * tx + j], 0.f);
        if (node < NN) {
            __half2 h0 = __floats2half2_rn(o[0], o[1]);
            __half2 h1 = __floats2half2_rn(o[2], o[3]);
            uint2 hv;
            hv.x = *(const unsigned int*)&h0;
            hv.y = *(const unsigned int*)&h1;
            Hw[node * 16 + tx] = hv;
            if (wfp32) {
                float4 ov = make_float4(o[0], o[1], o[2], o[3]);
                *(float4*)&out[node * 64 + 4 * tx] = ov;
            }
#pragma unroll
            for (int j = 0; j < 4; j++) {
                psum[j] += o[j];
                psq[j] = fmaf(o[j], o[j], psq[j]);
            }
        }
    }
#pragma unroll
    for (int j = 0; j < 4; j++) {
        sRed[ty][4 * tx + j] = psum[j];
        sRed[ty][64 + 4 * tx + j] = psq[j];
    }
    __syncthreads();
    if (tid < 128) {
        float s = 0.f;
#pragma unroll
        for (int r = 0; r < 16; r++) s += sRed[r][tid];
        atomicAdd(&g_bn[tid], s);
    }
}

// ---------------- fused pooling (mean+max, BN folded) + FC + log_softmax ----------------
__global__ void k_pool(const float* __restrict__ wfc, const float* __restrict__ bfc,
                       float* __restrict__ outp) {
    int g = blockIdx.x;
    int tid = threadIdx.x;  // 256 threads
    int r = tid >> 6;       // 0..3
    int c = tid & 63;
    __shared__ float ssum[4][64], smax[4][64], smin[4][64];
    __shared__ float sm[128];
    __shared__ float sz[6];
    const float* __restrict__ h = (const float*)g_bufA4;

    int s = g_gs[g], e = g_ge[g];
    float sum = 0.f, mx = -3.4e38f, mn = 3.4e38f;
    if (s >= 0) {
        for (int i = s + r; i <= e; i += 4) {
            float v = h[i * 64 + c];
            sum += v;
            mx = fmaxf(mx, v);
            mn = fminf(mn, v);
        }
    }
    ssum[r][c] = sum; smax[r][c] = mx; smin[r][c] = mn;
    __syncthreads();
    if (r == 0) {
        if (s >= 0) {
            float S = ssum[0][c] + ssum[1][c] + ssum[2][c] + ssum[3][c];
            float MX = fmaxf(fmaxf(smax[0][c], smax[1][c]), fmaxf(smax[2][c], smax[3][c]));
            float MN = fminf(fminf(smin[0][c], smin[1][c]), fminf(smin[2][c], smin[3][c]));
            float cnt = (float)(e - s + 1);
            float sc = g_sc[c], sh = g_sh[c];
            sm[c] = fmaf(sc, S / cnt, sh);
            sm[64 + c] = (sc >= 0.f) ? fmaf(sc, MX, sh) : fmaf(sc, MN, sh);
        } else {
            sm[c] = 0.f;
            sm[64 + c] = 0.f;
        }
    }
    __syncthreads();
    if (tid < 6) {
        float z = bfc[tid];
#pragma unroll 8
        for (int k = 0; k < 128; k++) z = fmaf(sm[k], wfc[k * 6 + tid], z);
        sz[tid] = z;
    }
    __syncthreads();
    if (tid == 0) {
        float m = sz[0];
#pragma unroll
        for (int j = 1; j < 6; j++) m = fmaxf(m, sz[j]);
        float se = 0.f;
#pragma unroll
        for (int j = 0; j < 6; j++) se += expf(sz[j] - m);
        float lse = m + logf(se);
#pragma unroll
        for (int j = 0; j < 6; j++) outp[g * 6 + j] = sz[j] - lse;
    }
}

// ---------------- launch ----------------
extern "C" void kernel_launch(void* const* d_in, const int* in_sizes, int n_in,
                              void* d_out, int out_size) {
    const float* x = (const float*)d_in[0];
    const int* ei = (const int*)d_in[1];
    const int* batch = (const int*)d_in[2];
    const float* w1a = (const float*)d_in[3];
    const float* b1a = (const float*)d_in[4];
    const float* w1b = (const float*)d_in[5];
    const float* b1b = (const float*)d_in[6];
    const float* w2a = (const float*)d_in[7];
    const float* b2a = (const float*)d_in[8];
    const float* w2b = (const float*)d_in[9];
    const float* b2b = (const float*)d_in[10];
    const float* w3a = (const float*)d_in[11];
    const float* b3a = (const float*)d_in[12];
    const float* w3b = (const float*)d_in[13];
    const float* b3b = (const float*)d_in[14];
    const float* eps1 = (const float*)d_in[15];
    const float* g1 = (const float*)d_in[16];
    const float* be1 = (const float*)d_in[17];
    const float* eps2 = (const float*)d_in[18];
    const float* g2 = (const float*)d_in[19];
    const float* be2 = (const float*)d_in[20];
    const float* eps3 = (const float*)d_in[21];
    const float* g3 = (const float*)d_in[22];
    const float* be3 = (const float*)d_in[23];
    const float* eps4 = (const float*)d_in[24];
    const float* g4 = (const float*)d_in[25];
    const float* be4 = (const float*)d_in[26];
    const float* wfc = (const float*)d_in[27];
    const float* bfc = (const float*)d_in[28];
    float* out = (float*)d_out;

    const int NB_E = (EE + 255) / 256;           // 12500 (== NN*32/256)
    const int NB_MLP = (NN + 63) / 64;           // 1563

    k_init<<<NBLK, 256>>>();
    k_toh_hist<<<NB_E, 256>>>((const float2*)x, ei);
    k_bounds_bsum<<<NBLK, 256>>>(batch);
    k_scanb<<<1, 512>>>();
    k_scan2<<<NBLK, 256>>>();
    k_scatter<<<NB_E, 256>>>(ei);

    // resolve device-global table addresses on host (graph-capturable: no sync)
    uint2 *h0, *h1;
    cudaGetSymbolAddress((void**)&h0, g_bufH0);
    cudaGetSymbolAddress((void**)&h1, g_bufH1);

    struct Layer {
        const float *wa, *ba, *wb, *bb, *eps, *g, *be;
    } layers[4] = {
        {w1a, b1a, w1b, b1b, eps1, g1, be1},
        {w2a, b2a, w2b, b2b, eps2, g2, be2},
        {w3a, b3a, w3b, b3b, eps3, g3, be3},
        {w3a, b3a, w3b, b3b, eps4, g4, be4},  // conv4 reuses nn3 weights
    };

    for (int l = 0; l < 4; l++) {
        const uint2* Hr = (l & 1) ? h1 : h0;
        uint2* Hw = (l & 1) ? h0 : h1;
        k_fused<<<NB_MLP, 256>>>(layers[l].wa, layers[l].ba, layers[l].wb, layers[l].bb,
                                 layers[l].eps, Hr, Hw, (l == 0) ? 0 : 1, (l == 3) ? 1 : 0);
        k_bnstats<<<1, 64>>>(layers[l].g, layers[l].be);
    }

    k_pool<<<GG, 256>>>(wfc, bfc, out);
}

// round 17
// speedup vs baseline: 1.2174x; 1.2174x over previous
#include <cuda_runtime.h>
#include <cuda_fp16.h>
#include <cuda_bf16.h>

#define NN 100000
#define EE 3200000
#define GG 512
#define NBLK 391   // (NN+255)/256

// ---------------- scratch (device globals; no allocations) ----------------
__device__ float4 g_bufA4[NN * 16];   // layer-4 MLP output (for pooling), fp32
__device__ uint2  g_bufH0[NN * 16];   // fp16 feature table, buffer 0 (128B rows)
__device__ uint2  g_bufH1[NN * 16];   // fp16 feature table, buffer 1
__device__ int    g_deg[NN];
__device__ int    g_rowptr[NN + 1];
__device__ int    g_cursor[NN];
__device__ int    g_col[EE];
__device__ int    g_gs[GG];
__device__ int    g_ge[GG];
__device__ float  g_bn[128];          // [0:64) sum, [64:128) sumsq
__device__ float  g_sc[64];           // BN folded scale
__device__ float  g_sh[64];           // BN folded shift
__device__ int    g_bsum[512];
__device__ int    g_boff[512];

// ---------------- f32x2 helpers ----------------
__device__ __forceinline__ unsigned long long pk2(float lo, float hi) {
    unsigned long long r;
    asm("mov.b64 %0,{%1,%2};" : "=l"(r) : "f"(lo), "f"(hi));
    return r;
}
__device__ __forceinline__ unsigned long long ffma2(unsigned long long a,
                                                    unsigned long long b,
                                                    unsigned long long c) {
    unsigned long long d;
    asm("fma.rn.f32x2 %0,%1,%2,%3;" : "=l"(d) : "l"(a), "l"(b), "l"(c));
    return d;
}
__device__ __forceinline__ void upk2(unsigned long long v, float& lo, float& hi) {
    asm("mov.b64 {%0,%1},%2;" : "=f"(lo), "=f"(hi) : "l"(v));
}

// ---------------- init ----------------
__global__ void k_init() {
    int i = blockIdx.x * blockDim.x + threadIdx.x;
    if (i < NN) g_deg[i] = 0;
    if (i < GG) { g_gs[i] = -1; g_ge[i] = -1; }
    if (i < 128) g_bn[i] = 0.f;
}

// ---------------- x -> fp16 table (buffer 0) AND edge histogram (EE == NN*32) --
__global__ void k_toh_hist(const float2* __restrict__ x2, const int* __restrict__ ei) {
    int i = blockIdx.x * blockDim.x + threadIdx.x;
    if (i < NN * 32) {
        float2 v = x2[i];
        ((__half2*)g_bufH0)[i] = __floats2half2_rn(v.x, v.y);
    }
    if (i < EE) atomicAdd(&g_deg[ei[EE + i]], 1);
}

// ---------------- graph bounds + per-block degree sums (both grid NBLK) -------
__global__ void k_bounds_bsum(const int* __restrict__ batch) {
    __shared__ int s[256];
    int t = threadIdx.x;
    int i = blockIdx.x * 256 + t;
    if (i < NN) {
        int b = batch[i];
        if (i == 0 || batch[i - 1] != b) g_gs[b] = i;
        if (i == NN - 1 || batch[i + 1] != b) g_ge[b] = i;
    }
    s[t] = (i < NN) ? g_deg[i] : 0;
    __syncthreads();
#pragma unroll
    for (int off = 128; off > 0; off >>= 1) {
        if (t < off) s[t] += s[t + off];
        __syncthreads();
    }
    if (t == 0) g_bsum[blockIdx.x] = s[0];
}

__global__ void k_scanb() {
    __shared__ int s[512];
    int t = threadIdx.x;
    int v = (t < NBLK) ? g_bsum[t] : 0;
    s[t] = v;
    __syncthreads();
    for (int off = 1; off < 512; off <<= 1) {
        int u = (t >= off) ? s[t - off] : 0;
        __syncthreads();
        s[t] += u;
        __syncthreads();
    }
    if (t < NBLK) g_boff[t] = s[t] - v;  // exclusive
}

__global__ void k_scan2() {
    __shared__ int s[256];
    int t = threadIdx.x;
    int i = blockIdx.x * 256 + t;
    int v = (i < NN) ? g_deg[i] : 0;
    s[t] = v;
    __syncthreads();
    for (int off = 1; off < 256; off <<= 1) {
        int u = (t >= off) ? s[t - off] : 0;
        __syncthreads();
        s[t] += u;
        __syncthreads();
    }
    int base = g_boff[blockIdx.x];
    int ex = base + s[t] - v;
    if (i < NN) { g_rowptr[i] = ex; g_cursor[i] = ex; }
    if (i == NN - 1) g_rowptr[NN] = base + s[t];
}

__global__ void k_scatter(const int* __restrict__ ei) {
    int e = blockIdx.x * blockDim.x + threadIdx.x;
    if (e >= EE) return;
    int s = ei[e];
    int d = ei[EE + e];
    int p = atomicAdd(&g_cursor[d], 1);
    g_col[p] = s;
}

// ---------------- BN stats -> folded affine, re-zero accumulators ----------------
__global__ void k_bnstats(const float* __restrict__ gam, const float* __restrict__ bet) {
    int c = threadIdx.x;  // 64 threads
    float inv = 1.0f / (float)NN;
    float mu = g_bn[c] * inv;
    float var = g_bn[64 + c] * inv - mu * mu;
    float s = gam[c] * rsqrtf(var + 1e-5f);
    g_sc[c] = s;
    g_sh[c] = bet[c] - mu * s;
    g_bn[c] = 0.f;
    g_bn[64 + c] = 0.f;
}

// ================= FUSED: gather(agg, BN-fold) + MLP + BN partial sums =========
// 64-node tile per block, 256 threads, min 3 blocks/SM (reg cap for occupancy).
// Double-buffered fp16 table (Hr -> Hw). Gather: half-warp per node, 2-deep ILP.
__global__ __launch_bounds__(256, 3) void k_fused(const float* __restrict__ wa,
                                                  const float* __restrict__ ba,
                                                  const float* __restrict__ wb,
                                                  const float* __restrict__ bb,
                                                  const float* __restrict__ epsp,
                                                  const uint2* __restrict__ Hr,
                                                  uint2* __restrict__ Hw,
                                                  int fold, int wfp32) {
    __shared__ float sT[64][68];     // transposed tile sT[k][node]
    __shared__ float sW[64 * 64];    // weights; later reused as BN-reduce buffer
    __shared__ float sB[64];

    float* __restrict__ out = (float*)g_bufA4;

    int tid = threadIdx.x;
    int n0 = blockIdx.x * 64;
    float e1 = 1.0f + *epsp;

    // issue wa/ba loads first so they land under gather latency
    for (int idx = tid; idx < 4096; idx += 256) sW[idx] = wa[idx];
    if (tid < 64) sB[tid] = ba[tid];

    // ---- phase 0: gather + fold (2-deep load ILP; lowest reg pressure) ----
    {
        int hw = tid >> 4;       // half-warp id 0..15
        int li = tid & 15;       // lane within half-warp: 4 channels
        float4 fsc, fsh;
        if (fold) {
            fsc = *(const float4*)&g_sc[li * 4];
            fsh = *(const float4*)&g_sh[li * 4];
        }
#pragma unroll
        for (int rr = 0; rr < 4; rr++) {
            int r = hw + rr * 16;
            int node = n0 + r;
            float4 a0 = make_float4(0.f, 0.f, 0.f, 0.f);
            if (node < NN) {
                uint2 sv = Hr[node * 16 + li];
                float2 s0 = __half22float2(*(const __half2*)&sv.x);
                float2 s1 = __half22float2(*(const __half2*)&sv.y);
                a0 = make_float4(e1 * s0.x, e1 * s0.y, e1 * s1.x, e1 * s1.y);
                float4 a1 = make_float4(0.f, 0.f, 0.f, 0.f);
                int s = g_rowptr[node], e = g_rowptr[node + 1];
                int j = s;
                for (; j + 1 < e; j += 2) {
                    int m0 = __ldg(&g_col[j]);
                    int m1 = __ldg(&g_col[j + 1]);
                    uint2 v0 = Hr[m0 * 16 + li];
                    uint2 v1 = Hr[m1 * 16 + li];
                    float2 p0 = __half22float2(*(const __half2*)&v0.x);
                    float2 p1 = __half22float2(*(const __half2*)&v0.y);
                    float2 q0 = __half22float2(*(const __half2*)&v1.x);
                    float2 q1 = __half22float2(*(const __half2*)&v1.y);
                    a0.x += p0.x; a0.y += p0.y; a0.z += p1.x; a0.w += p1.y;
                    a1.x += q0.x; a1.y += q0.y; a1.z += q1.x; a1.w += q1.y;
                }
                if (j < e) {
                    int m0 = __ldg(&g_col[j]);
                    uint2 v0 = Hr[m0 * 16 + li];
                    float2 p0 = __half22float2(*(const __half2*)&v0.x);
                    float2 p1 = __half22float2(*(const __half2*)&v0.y);
                    a0.x += p0.x; a0.y += p0.y; a0.z += p1.x; a0.w += p1.y;
                }
                a0.x += a1.x; a0.y += a1.y; a0.z += a1.z; a0.w += a1.w;
                if (fold) {
                    float coef = e1 + (float)(e - s);
                    a0.x = fmaf(a0.x, fsc.x, coef * fsh.x);
                    a0.y = fmaf(a0.y, fsc.y, coef * fsh.y);
                    a0.z = fmaf(a0.z, fsc.z, coef * fsh.z);
                    a0.w = fmaf(a0.w, fsc.w, coef * fsh.w);
                }
            }
            sT[4 * li + 0][r] = a0.x;
            sT[4 * li + 1][r] = a0.y;
            sT[4 * li + 2][r] = a0.z;
            sT[4 * li + 3][r] = a0.w;
        }
    }
    __syncthreads();

    int tx = tid & 15;   // channel quad
    int ty = tid >> 4;   // node quad

    unsigned long long accP[4][2];
#pragma unroll
    for (int i = 0; i < 4; i++) { accP[i][0] = 0ULL; accP[i][1] = 0ULL; }

#pragma unroll 16
    for (int k = 0; k < 64; k++) {
        float4 a = *(const float4*)&sT[k][ty * 4];
        ulonglong2 b2 = *(const ulonglong2*)(sW + k * 64 + tx * 4);
        float av[4] = {a.x, a.y, a.z, a.w};
#pragma unroll
        for (int i = 0; i < 4; i++) {
            unsigned long long aa = pk2(av[i], av[i]);
            accP[i][0] = ffma2(aa, b2.x, accP[i][0]);
            accP[i][1] = ffma2(aa, b2.y, accP[i][1]);
        }
    }
    __syncthreads();  // all reads of sT/sW done

    // mid = relu(acc + ba), stored transposed back into sT
    {
        float m[4][4];
#pragma unroll
        for (int i = 0; i < 4; i++) {
            upk2(accP[i][0], m[i][0], m[i][1]);
            upk2(accP[i][1], m[i][2], m[i][3]);
        }
#pragma unroll
        for (int j = 0; j < 4; j++) {
            float bias = sB[4 * tx + j];
            float4 w;
            w.x = fmaxf(m[0][j] + bias, 0.f);
            w.y = fmaxf(m[1][j] + bias, 0.f);
            w.z = fmaxf(m[2][j] + bias, 0.f);
            w.w = fmaxf(m[3][j] + bias, 0.f);
            *(float4*)&sT[4 * tx + j][4 * ty] = w;
        }
    }
    for (int idx = tid; idx < 4096; idx += 256) sW[idx] = wb[idx];
    if (tid < 64) sB[tid] = bb[tid];
    __syncthreads();

#pragma unroll
    for (int i = 0; i < 4; i++) { accP[i][0] = 0ULL; accP[i][1] = 0ULL; }

#pragma unroll 16
    for (int k = 0; k < 64; k++) {
        float4 a = *(const float4*)&sT[k][ty * 4];
        ulonglong2 b2 = *(const ulonglong2*)(sW + k * 64 + tx * 4);
        float av[4] = {a.x, a.y, a.z, a.w};
#pragma unroll
        for (int i = 0; i < 4; i++) {
            unsigned long long aa = pk2(av[i], av[i]);
            accP[i][0] = ffma2(aa, b2.x, accP[i][0]);
            accP[i][1] = ffma2(aa, b2.y, accP[i][1]);
        }
    }
    __syncthreads();  // sW reads done -> safe to reuse as sRed

    float (*sRed)[128] = (float (*)[128])sW;  // alias

    // out = relu(acc2 + bb): fp16 table write (layers 1-3) or fp32 (layer 4) + BN partials
    float m2[4][4];
#pragma unroll
    for (int i = 0; i < 4; i++) {
        upk2(accP[i][0], m2[i][0], m2[i][1]);
        upk2(accP[i][1], m2[i][2], m2[i][3]);
    }
    float psum[4] = {0.f, 0.f, 0.f, 0.f};
    float psq[4] = {0.f, 0.f, 0.f, 0.f};
#pragma unroll
    for (int i = 0; i < 4; i++) {
        int node = n0 + 4 * ty + i;
        float o[4];
#pragma unroll
        for (int j = 0; j < 4; j++) o[j] = fmaxf(m2[i][j] + sB[4 * tx + j], 0.f);
        if (node < NN) {
            if (wfp32) {
                float4 ov = make_float4(o[0], o[1], o[2], o[3]);
                *(float4*)&out[node * 64 + 4 * tx] = ov;
            } else {
                __half2 h0 = __floats2half2_rn(o[0], o[1]);
                __half2 h1 = __floats2half2_rn(o[2], o[3]);
                uint2 hv;
                hv.x = *(const unsigned int*)&h0;
                hv.y = *(const unsigned int*)&h1;
                Hw[node * 16 + tx] = hv;
            }
#pragma unroll
            for (int j = 0; j < 4; j++) {
                psum[j] += o[j];
                psq[j] = fmaf(o[j], o[j], psq[j]);
            }
        }
    }
#pragma unroll
    for (int j = 0; j < 4; j++) {
        sRed[ty][4 * tx + j] = psum[j];
        sRed[ty][64 + 4 * tx + j] = psq[j];
    }
    __syncthreads();
    if (tid < 128) {
        float s = 0.f;
#pragma unroll
        for (int r = 0; r < 16; r++) s += sRed[r][tid];
        atomicAdd(&g_bn[tid], s);
    }
}

// ---------------- fused pooling (mean+max, BN folded) + FC + log_softmax ----------------
__global__ void k_pool(const float* __restrict__ wfc, const float* __restrict__ bfc,
                       float* __restrict__ outp) {
    int g = blockIdx.x;
    int tid = threadIdx.x;  // 256 threads
    int r = tid >> 6;       // 0..3
    int c = tid & 63;
    __shared__ float ssum[4][64], smax[4][64], smin[4][64];
    __shared__ float sm[128];
    __shared__ float sz[6];
    const float* __restrict__ h = (const float*)g_bufA4;

    int s = g_gs[g], e = g_ge[g];
    float sum = 0.f, mx = -3.4e38f, mn = 3.4e38f;
    if (s >= 0) {
        for (int i = s + r; i <= e; i += 4) {
            float v = h[i * 64 + c];
            sum += v;
            mx = fmaxf(mx, v);
            mn = fminf(mn, v);
        }
    }
    ssum[r][c] = sum; smax[r][c] = mx; smin[r][c] = mn;
    __syncthreads();
    if (r == 0) {
        if (s >= 0) {
            float S = ssum[0][c] + ssum[1][c] + ssum[2][c] + ssum[3][c];
            float MX = fmaxf(fmaxf(smax[0][c], smax[1][c]), fmaxf(smax[2][c], smax[3][c]));
            float MN = fminf(fminf(smin[0][c], smin[1][c]), fminf(smin[2][c], smin[3][c]));
            float cnt = (float)(e - s + 1);
            float sc = g_sc[c], sh = g_sh[c];
            sm[c] = fmaf(sc, S / cnt, sh);
            sm[64 + c] = (sc >= 0.f) ? fmaf(sc, MX, sh) : fmaf(sc, MN, sh);
        } else {
            sm[c] = 0.f;
            sm[64 + c] = 0.f;
        }
    }
    __syncthreads();
    if (tid < 6) {
        float z = bfc[tid];
#pragma unroll 8
        for (int k = 0; k < 128; k++) z = fmaf(sm[k], wfc[k * 6 + tid], z);
        sz[tid] = z;
    }
    __syncthreads();
    if (tid == 0) {
        float m = sz[0];
#pragma unroll
        for (int j = 1; j < 6; j++) m = fmaxf(m, sz[j]);
        float se = 0.f;
#pragma unroll
        for (int j = 0; j < 6; j++) se += expf(sz[j] - m);
        float lse = m + logf(se);
#pragma unroll
        for (int j = 0; j < 6; j++) outp[g * 6 + j] = sz[j] - lse;
    }
}

// ---------------- launch ----------------
extern "C" void kernel_launch(void* const* d_in, const int* in_sizes, int n_in,
                              void* d_out, int out_size) {
    const float* x = (const float*)d_in[0];
    const int* ei = (const int*)d_in[1];
    const int* batch = (const int*)d_in[2];
    const float* w1a = (const float*)d_in[3];
    const float* b1a = (const float*)d_in[4];
    const float* w1b = (const float*)d_in[5];
    const float* b1b = (const float*)d_in[6];
    const float* w2a = (const float*)d_in[7];
    const float* b2a = (const float*)d_in[8];
    const float* w2b = (const float*)d_in[9];
    const float* b2b = (const float*)d_in[10];
    const float* w3a = (const float*)d_in[11];
    const float* b3a = (const float*)d_in[12];
    const float* w3b = (const float*)d_in[13];
    const float* b3b = (const float*)d_in[14];
    const float* eps1 = (const float*)d_in[15];
    const float* g1 = (const float*)d_in[16];
    const float* be1 = (const float*)d_in[17];
    const float* eps2 = (const float*)d_in[18];
    const float* g2 = (const float*)d_in[19];
    const float* be2 = (const float*)d_in[20];
    const float* eps3 = (const float*)d_in[21];
    const float* g3 = (const float*)d_in[22];
    const float* be3 = (const float*)d_in[23];
    const float* eps4 = (const float*)d_in[24];
    const float* g4 = (const float*)d_in[25];
    const float* be4 = (const float*)d_in[26];
    const float* wfc = (const float*)d_in[27];
    const float* bfc = (const float*)d_in[28];
    float* out = (float*)d_out;

    const int NB_E = (EE + 255) / 256;           // 12500 (== NN*32/256)
    const int NB_MLP = (NN + 63) / 64;           // 1563

    k_init<<<NBLK, 256>>>();
    k_toh_hist<<<NB_E, 256>>>((const float2*)x, ei);
    k_bounds_bsum<<<NBLK, 256>>>(batch);
    k_scanb<<<1, 512>>>();
    k_scan2<<<NBLK, 256>>>();
    k_scatter<<<NB_E, 256>>>(ei);

    // resolve device-global table addresses on host (graph-capturable: no sync)
    uint2 *h0, *h1;
    cudaGetSymbolAddress((void**)&h0, g_bufH0);
    cudaGetSymbolAddress((void**)&h1, g_bufH1);

    struct Layer {
        const float *wa, *ba, *wb, *bb, *eps, *g, *be;
    } layers[4] = {
        {w1a, b1a, w1b, b1b, eps1, g1, be1},
        {w2a, b2a, w2b, b2b, eps2, g2, be2},
        {w3a, b3a, w3b, b3b, eps3, g3, be3},
        {w3a, b3a, w3b, b3b, eps4, g4, be4},  // conv4 reuses nn3 weights
    };

    for (int l = 0; l < 4; l++) {
        const uint2* Hr = (l & 1) ? h1 : h0;
        uint2* Hw = (l & 1) ? h0 : h1;
        k_fused<<<NB_MLP, 256>>>(layers[l].wa, layers[l].ba, layers[l].wb, layers[l].bb,
                                 layers[l].eps, Hr, Hw, (l == 0) ? 0 : 1, (l == 3) ? 1 : 0);
        k_bnstats<<<1, 64>>>(layers[l].g, layers[l].be);
    }

    k_pool<<<GG, 256>>>(wfc, bfc, out);
}